// round 16
// baseline (speedup 1.0000x reference)
#include <cuda_runtime.h>
#include <math.h>

#define TT 2048
#define BB 64
#define DD 256
#define HH 512

#define NGROUPS 8
#define GC 16         // CTAs per group
#define GB 8          // batch elems per group
#define JC 32         // output columns owned per CTA
#define NT 256        // 8 warps
#define HROW 520      // hbuf row stride (floats), 16B-aligned

// ---------------- packed fp32x2 helpers ----------------
#define FMA_X2(d, a, b, c) \
    asm("fma.rn.f32x2 %0, %1, %2, %3;" : "=l"(d) : "l"(a), "l"(b), "l"(c))
#define ADD_X2(d, a, b) \
    asm("add.rn.f32x2 %0, %1, %2;" : "=l"(d) : "l"(a), "l"(b))
#define DUP_X2(d, s) \
    asm("mov.b64 %0, {%1, %1};" : "=l"(d) : "r"(__float_as_uint(s)))
#define UNPACK_X2(lo, hi, p) \
    asm("mov.b64 {%0, %1}, %2;" : "=r"(lo), "=r"(hi) : "l"(p))

// ---------------- device scratch ----------------
__device__ float g_Gx[(size_t)TT * 3 * BB * HH];
__device__ float g_h[BB * HH];
__device__ float g_rh[BB * HH];
__device__ unsigned g_bcnt[NGROUPS];   // monotonic arrive counter
__device__ unsigned g_bgen[NGROUPS];   // monotonic generation

// ---------------- slim group barrier (R15-proven: monotonic, no reset) --------------
__device__ __forceinline__ void group_barrier(int grp) {
    __syncthreads();
    if (threadIdx.x == 0) {
        unsigned old;
        asm volatile("atom.acq_rel.gpu.global.add.u32 %0, [%1], %2;"
                     : "=r"(old) : "l"(&g_bcnt[grp]), "r"(1u));
        unsigned target = old / GC + 1u;
        if (old % GC == GC - 1u) {
            asm volatile("st.release.gpu.global.u32 [%0], %1;"
                         :: "l"(&g_bgen[grp]), "r"(target));
        } else {
            unsigned cur;
            do {
                asm volatile("ld.acquire.gpu.global.u32 %0, [%1];"
                             : "=r"(cur) : "l"(&g_bgen[grp]));
            } while (cur < target);
        }
    }
    __syncthreads();
}

// ---------------- fast activations (R15-proven) ----------------
__device__ __forceinline__ float fast_sigmoid(float x) {
    return __fdividef(1.f, 1.f + __expf(-x));
}
__device__ __forceinline__ float fast_tanh(float x) {
    return __fdividef(2.f, 1.f + __expf(-2.f * x)) - 1.f;
}

// =====================================================================================
// Phase 1 (R5-proven, unchanged)
// =====================================================================================
__global__ void __launch_bounds__(256) phase1_gemm(
    const float* __restrict__ x,
    const float* __restrict__ Wz, const float* __restrict__ bz,
    const float* __restrict__ Wr, const float* __restrict__ br,
    const float* __restrict__ Wh, const float* __restrict__ bh)
{
    __shared__ float xs[32 * 132];
    __shared__ float ws[32 * 64];

    const int gate = blockIdx.y >> 3;
    const int jt0  = (blockIdx.y & 7) * 64;
    const float* W    = (gate == 0) ? Wz : ((gate == 1) ? Wr : Wh);
    const float* bias = (gate == 0) ? bz : ((gate == 1) ? br : bh);
    const int m0  = blockIdx.x * 128;
    const int tid = threadIdx.x;
    const int tn = tid & 15;
    const int tm = tid >> 4;

    unsigned long long pa[4][4];
#pragma unroll
    for (int i = 0; i < 4; i++)
#pragma unroll
        for (int j = 0; j < 4; j++) pa[i][j] = 0ull;

    for (int kc = 0; kc < 8; kc++) {
#pragma unroll
        for (int i = 0; i < 16; i++) {
            int idx = tid + i * 256;
            int row = idx >> 5, kk = idx & 31;
            xs[kk * 132 + row] = x[(size_t)(m0 + row) * DD + kc * 32 + kk];
        }
#pragma unroll
        for (int i = 0; i < 8; i++) {
            int idx = tid + i * 256;
            int kk = idx >> 6, jj = idx & 63;
            ws[kk * 64 + jj] = W[(size_t)(kc * 32 + kk) * HH + jt0 + jj];
        }
        __syncthreads();
#pragma unroll 8
        for (int kk = 0; kk < 32; kk++) {
            float4 w4 = *(const float4*)&ws[kk * 64 + tn * 4];
            ulonglong2 xL = *(const ulonglong2*)&xs[kk * 132 + tm * 8];
            ulonglong2 xH = *(const ulonglong2*)&xs[kk * 132 + tm * 8 + 4];
            unsigned long long hp[4] = {xL.x, xL.y, xH.x, xH.y};
            unsigned long long wd[4];
            DUP_X2(wd[0], w4.x); DUP_X2(wd[1], w4.y);
            DUP_X2(wd[2], w4.z); DUP_X2(wd[3], w4.w);
#pragma unroll
            for (int i = 0; i < 4; i++)
#pragma unroll
                for (int j = 0; j < 4; j++)
                    FMA_X2(pa[i][j], hp[i], wd[j], pa[i][j]);
        }
        __syncthreads();
    }

#pragma unroll
    for (int i = 0; i < 4; i++) {
#pragma unroll
        for (int j = 0; j < 4; j++) {
            unsigned lo, hi;
            UNPACK_X2(lo, hi, pa[i][j]);
            float bj = bias[jt0 + tn * 4 + j];
            int mA = m0 + tm * 8 + 2 * i;
            int tA = mA >> 6, bA = mA & 63;
            g_Gx[(((size_t)tA * 3 + gate) * BB + bA) * HH + jt0 + tn * 4 + j] =
                __uint_as_float(lo) + bj;
            int mB = mA + 1;
            int tB = mB >> 6, bB = mB & 63;
            g_Gx[(((size_t)tB * 3 + gate) * BB + bB) * HH + jt0 + tn * 4 + j] =
                __uint_as_float(hi) + bj;
        }
    }
}

// =====================================================================================
// Phase 2: k-packed layout. hbuf[b][k] plain rows (HROW pad); weights TRANSPOSED
// wT[col][k] (512 floats/row, no pad, no swizzle). FMA2 packs adjacent k from both
// operands -> zero DUPs. Fills: 4x LDG.128 + 4x STS.128 per thread, conflict-free.
// Stage1: warp w -> gate=w>>2, jt=w&3; two passes p over cols jt*8+4p..+4;
//   32 packed accs v=b*4+jj; R5 butterfly -> lane owns v=lane (b=lane>>2, jj=lane&3);
//   fold lo+hi over the k-pair.
// Stage2: warp w -> cols 4w..4w+4, full K, single pass, same reduction.
// =====================================================================================
__global__ void __launch_bounds__(NT, 1) phase2_gru(
    const float* __restrict__ h0in,
    const float* __restrict__ Wz,
    const float* __restrict__ Wr,
    const float* __restrict__ Wh,
    float* __restrict__ out)
{
    extern __shared__ float sm[];
    float* wzT  = sm;                      // [32][512]
    float* wrT  = wzT + JC * HH;
    float* whT  = wrT + JC * HH;
    float* hbuf = whT + JC * HH;           // [8][HROW]
    float* z_s  = hbuf + GB * HROW;        // [8][32]
    float* ho_s = z_s + GB * JC;           // [8][32]

    const int grp  = blockIdx.x >> 4;
    const int rank = blockIdx.x & 15;
    const int b0 = grp * GB;
    const int j0 = rank * JC;
    const int tid  = threadIdx.x;
    const int warp = tid >> 5;
    const int lane = tid & 31;

    // ---- load TRANSPOSED recurrent weights: wT[j][k] = W[DD+k][j0+j] ----
    {
        const int j  = tid & 31;       // lane -> col (coalesced LDG)
        const int ks = tid >> 5;       // 8 k-slices of 64
        for (int m = 0; m < 3; m++) {
            const float* Wsrc = (m == 0) ? Wz : ((m == 1) ? Wr : Wh);
            float* wdst = (m == 0) ? wzT : ((m == 1) ? wrT : whT);
            for (int kk = ks * 64; kk < ks * 64 + 64; kk++)
                wdst[j * HH + kk] = Wsrc[(size_t)(DD + kk) * HH + j0 + j];
        }
    }
    __syncthreads();

    const int gate1 = warp >> 2;           // stage1: 0=z, 1=r
    const int jt    = warp & 3;            // stage1 8-col tile (two 4-col passes)
    const int rb    = lane >> 2;           // owned batch after reduction
    const int rj    = lane & 3;            // owned jj after reduction
    const int fb    = warp;                // fill: row = warp
    const int fl    = lane;                // fill: lane chunk

    for (int t = 0; t < TT; t++) {
        // ---- Gx prefetch ----
        float gxA, gxB, gx2;
        {
            size_t r1 = (((size_t)t * 3 + gate1) * BB + b0 + rb) * HH + j0 + jt * 8 + rj;
            gxA = __ldg(&g_Gx[r1]);          // pass 0 col
            gxB = __ldg(&g_Gx[r1 + 4]);      // pass 1 col (+4)
            size_t r2 = (((size_t)t * 3 + 2) * BB + b0 + rb) * HH + j0 + warp * 4 + rj;
            gx2 = __ldg(&g_Gx[r2]);
        }

        // ---- fill hbuf with h: 4x LDG.128 + 4x STS.128, conflict-free ----
        const float* hsrc = (t == 0) ? h0in : (const float*)g_h;
#pragma unroll
        for (int c = 0; c < 4; c++) {
            int k = c * 128 + fl * 4;
            float4 v = __ldcg((const float4*)&hsrc[(size_t)(b0 + fb) * HH + k]);
            *(float4*)&hbuf[fb * HROW + k] = v;
        }
        __syncthreads();

        // stash h_old for own columns
        { int b = tid >> 5, jl = tid & 31; ho_s[tid] = hbuf[b * HROW + j0 + jl]; }

        // ================= stage 1: two 4-col passes over full K =================
#pragma unroll
        for (int p = 0; p < 2; p++) {
            const int cbase = jt * 8 + p * 4;
            unsigned long long a2[32];
#pragma unroll
            for (int v = 0; v < 32; v++) a2[v] = 0ull;
            {
                const float* wg = gate1 ? wrT : wzT;
#pragma unroll
                for (int i = 0; i < 4; i++) {
                    int k = i * 128 + lane * 4;
                    ulonglong2 w2[4];
#pragma unroll
                    for (int jj = 0; jj < 4; jj++)
                        w2[jj] = *(const ulonglong2*)&wg[(cbase + jj) * HH + k];
#pragma unroll
                    for (int b = 0; b < 8; b++) {
                        ulonglong2 h2 = *(const ulonglong2*)&hbuf[b * HROW + k];
#pragma unroll
                        for (int jj = 0; jj < 4; jj++) {
                            FMA_X2(a2[b * 4 + jj], h2.x, w2[jj].x, a2[b * 4 + jj]);
                            FMA_X2(a2[b * 4 + jj], h2.y, w2[jj].y, a2[b * 4 + jj]);
                        }
                    }
                }
            }
            // R5 butterfly (32 packed, 5 splits): lane owns v = lane
#pragma unroll
            for (int s = 0; s < 5; s++) {
                const int m = 16 >> s, half = 16 >> s;
                bool up = (lane & m) != 0;
#pragma unroll
                for (int i = 0; i < half; i++) {
                    unsigned long long send = up ? a2[i] : a2[i + half];
                    unsigned long long r = __shfl_xor_sync(0xffffffffu, send, m);
                    unsigned long long keep = up ? a2[i + half] : a2[i];
                    ADD_X2(a2[i], keep, r);
                }
            }
            {
                unsigned lo, hi;
                UNPACK_X2(lo, hi, a2[0]);
                float sum = __uint_as_float(lo) + __uint_as_float(hi);
                float pre = sum + (p == 0 ? gxA : gxB);
                float s = fast_sigmoid(pre);
                int col = cbase + rj;
                if (gate1 == 0) {
                    z_s[rb * JC + col] = s;
                } else {
                    float rh = s * hbuf[rb * HROW + j0 + col];
                    __stcg(&g_rh[(size_t)(b0 + rb) * HH + j0 + col], rh);
                }
            }
        }

        group_barrier(grp);   // rh complete group-wide

        // ================= stage 2: fill hbuf with r*h =================
#pragma unroll
        for (int c = 0; c < 4; c++) {
            int k = c * 128 + fl * 4;
            float4 v = __ldcg((const float4*)&g_rh[(size_t)(b0 + fb) * HH + k]);
            *(float4*)&hbuf[fb * HROW + k] = v;
        }
        __syncthreads();

        // stage-2 dot: warp owns cols 4w..4w+4, full K
        unsigned long long a2[32];
#pragma unroll
        for (int v = 0; v < 32; v++) a2[v] = 0ull;
        {
            const int cbase = warp * 4;
#pragma unroll
            for (int i = 0; i < 4; i++) {
                int k = i * 128 + lane * 4;
                ulonglong2 w2[4];
#pragma unroll
                for (int jj = 0; jj < 4; jj++)
                    w2[jj] = *(const ulonglong2*)&whT[(cbase + jj) * HH + k];
#pragma unroll
                for (int b = 0; b < 8; b++) {
                    ulonglong2 h2 = *(const ulonglong2*)&hbuf[b * HROW + k];
#pragma unroll
                    for (int jj = 0; jj < 4; jj++) {
                        FMA_X2(a2[b * 4 + jj], h2.x, w2[jj].x, a2[b * 4 + jj]);
                        FMA_X2(a2[b * 4 + jj], h2.y, w2[jj].y, a2[b * 4 + jj]);
                    }
                }
            }
        }
#pragma unroll
        for (int s = 0; s < 5; s++) {
            const int m = 16 >> s, half = 16 >> s;
            bool up = (lane & m) != 0;
#pragma unroll
            for (int i = 0; i < half; i++) {
                unsigned long long send = up ? a2[i] : a2[i + half];
                unsigned long long r = __shfl_xor_sync(0xffffffffu, send, m);
                unsigned long long keep = up ? a2[i + half] : a2[i];
                ADD_X2(a2[i], keep, r);
            }
        }
        {
            unsigned lo, hi;
            UNPACK_X2(lo, hi, a2[0]);
            float sum = __uint_as_float(lo) + __uint_as_float(hi);
            int col = warp * 4 + rj;
            float ht = fast_tanh(sum + gx2);
            float z  = z_s[rb * JC + col];
            float ho = ho_s[rb * JC + col];
            float hn = ho + z * (ht - ho);
            __stcg(&g_h[(size_t)(b0 + rb) * HH + j0 + col], hn);
            out[((size_t)t * BB + b0 + rb) * HH + j0 + col] = hn;
        }

        group_barrier(grp);   // h complete before next step
    }
}

// =====================================================================================
extern "C" void kernel_launch(void* const* d_in, const int* in_sizes, int n_in,
                              void* d_out, int out_size)
{
    const float* x  = (const float*)d_in[0];
    const float* h0 = (const float*)d_in[1];
    const float* Wz = (const float*)d_in[2];
    const float* bz = (const float*)d_in[3];
    const float* Wr = (const float*)d_in[4];
    const float* br = (const float*)d_in[5];
    const float* Wh = (const float*)d_in[6];
    const float* bh = (const float*)d_in[7];
    float* out = (float*)d_out;

    const int smem_bytes = (3 * JC * HH + GB * HROW + 2 * GB * JC) * (int)sizeof(float);
    cudaFuncSetAttribute(phase2_gru, cudaFuncAttributeMaxDynamicSharedMemorySize, smem_bytes);

    dim3 g1((TT * BB) / 128, 24);
    phase1_gemm<<<g1, 256>>>(x, Wz, bz, Wr, br, Wh, bh);

    phase2_gru<<<NGROUPS * GC, NT, smem_bytes>>>(h0, Wz, Wr, Wh, out);
}

// round 17
// speedup vs baseline: 1.0641x; 1.0641x over previous
#include <cuda_runtime.h>
#include <math.h>

#define TT 2048
#define BB 64
#define DD 256
#define HH 512

#define NGROUPS 8
#define GC 16         // CTAs per group
#define GB 8          // batch elems per group
#define JC 32         // output columns owned per CTA
#define NT 256        // 8 warps
#define HPAD 12       // hbuf row pad (16B-aligned rows, conflict-free LDS.128)

// ---------------- packed fp32x2 helpers ----------------
#define FMA_X2(d, a, b, c) \
    asm("fma.rn.f32x2 %0, %1, %2, %3;" : "=l"(d) : "l"(a), "l"(b), "l"(c))
#define ADD_X2(d, a, b) \
    asm("add.rn.f32x2 %0, %1, %2;" : "=l"(d) : "l"(a), "l"(b))
#define DUP_X2(d, s) \
    asm("mov.b64 %0, {%1, %1};" : "=l"(d) : "r"(__float_as_uint(s)))
#define UNPACK_X2(lo, hi, p) \
    asm("mov.b64 {%0, %1}, %2;" : "=r"(lo), "=r"(hi) : "l"(p))

// ---------------- device scratch ----------------
__device__ float g_Gx[(size_t)TT * 3 * BB * HH];
__device__ float g_h[BB * HH];
__device__ float g_rh[BB * HH];
__device__ unsigned g_icnt[NGROUPS];   // init barrier: monotonic counter
__device__ unsigned g_igen[NGROUPS];   // init barrier: monotonic generation
__device__ unsigned g_scnt[NGROUPS];   // step counter (reset each launch pre-init-bar)

// ---------------- init barrier (R15-proven monotonic logic; replay-safe) -------------
__device__ __forceinline__ void init_barrier(int grp) {
    __syncthreads();
    if (threadIdx.x == 0) {
        unsigned old;
        asm volatile("atom.acq_rel.gpu.global.add.u32 %0, [%1], %2;"
                     : "=r"(old) : "l"(&g_icnt[grp]), "r"(1u));
        unsigned target = old / GC + 1u;
        if (old % GC == GC - 1u) {
            asm volatile("st.release.gpu.global.u32 [%0], %1;"
                         :: "l"(&g_igen[grp]), "r"(target));
        } else {
            unsigned cur;
            do {
                asm volatile("ld.acquire.gpu.global.u32 %0, [%1];"
                             : "=r"(cur) : "l"(&g_igen[grp]));
            } while (cur < target);
        }
    }
    __syncthreads();
}

// ---------------- step barrier: fire-and-forget red + static-target poll -------------
__device__ __forceinline__ void step_barrier(int grp, unsigned target) {
    __syncthreads();   // all CTA work (incl. L2 stores) before the release-red
    if (threadIdx.x == 0) {
        asm volatile("red.release.gpu.global.add.u32 [%0], %1;"
                     :: "l"(&g_scnt[grp]), "r"(1u));
        unsigned cur;
        do {
            asm volatile("ld.acquire.gpu.global.u32 %0, [%1];"
                         : "=r"(cur) : "l"(&g_scnt[grp]));
        } while (cur < target);
    }
    __syncthreads();
}

// ---------------- fast activations (R15-proven) ----------------
__device__ __forceinline__ float fast_sigmoid(float x) {
    return __fdividef(1.f, 1.f + __expf(-x));
}
__device__ __forceinline__ float fast_tanh(float x) {
    return __fdividef(2.f, 1.f + __expf(-2.f * x)) - 1.f;
}

// =====================================================================================
// Phase 1 (R5-proven, unchanged)
// =====================================================================================
__global__ void __launch_bounds__(256) phase1_gemm(
    const float* __restrict__ x,
    const float* __restrict__ Wz, const float* __restrict__ bz,
    const float* __restrict__ Wr, const float* __restrict__ br,
    const float* __restrict__ Wh, const float* __restrict__ bh)
{
    __shared__ float xs[32 * 132];
    __shared__ float ws[32 * 64];

    const int gate = blockIdx.y >> 3;
    const int jt0  = (blockIdx.y & 7) * 64;
    const float* W    = (gate == 0) ? Wz : ((gate == 1) ? Wr : Wh);
    const float* bias = (gate == 0) ? bz : ((gate == 1) ? br : bh);
    const int m0  = blockIdx.x * 128;
    const int tid = threadIdx.x;
    const int tn = tid & 15;
    const int tm = tid >> 4;

    unsigned long long pa[4][4];
#pragma unroll
    for (int i = 0; i < 4; i++)
#pragma unroll
        for (int j = 0; j < 4; j++) pa[i][j] = 0ull;

    for (int kc = 0; kc < 8; kc++) {
#pragma unroll
        for (int i = 0; i < 16; i++) {
            int idx = tid + i * 256;
            int row = idx >> 5, kk = idx & 31;
            xs[kk * 132 + row] = x[(size_t)(m0 + row) * DD + kc * 32 + kk];
        }
#pragma unroll
        for (int i = 0; i < 8; i++) {
            int idx = tid + i * 256;
            int kk = idx >> 6, jj = idx & 63;
            ws[kk * 64 + jj] = W[(size_t)(kc * 32 + kk) * HH + jt0 + jj];
        }
        __syncthreads();
#pragma unroll 8
        for (int kk = 0; kk < 32; kk++) {
            float4 w4 = *(const float4*)&ws[kk * 64 + tn * 4];
            ulonglong2 xL = *(const ulonglong2*)&xs[kk * 132 + tm * 8];
            ulonglong2 xH = *(const ulonglong2*)&xs[kk * 132 + tm * 8 + 4];
            unsigned long long hp[4] = {xL.x, xL.y, xH.x, xH.y};
            unsigned long long wd[4];
            DUP_X2(wd[0], w4.x); DUP_X2(wd[1], w4.y);
            DUP_X2(wd[2], w4.z); DUP_X2(wd[3], w4.w);
#pragma unroll
            for (int i = 0; i < 4; i++)
#pragma unroll
                for (int j = 0; j < 4; j++)
                    FMA_X2(pa[i][j], hp[i], wd[j], pa[i][j]);
        }
        __syncthreads();
    }

#pragma unroll
    for (int i = 0; i < 4; i++) {
#pragma unroll
        for (int j = 0; j < 4; j++) {
            unsigned lo, hi;
            UNPACK_X2(lo, hi, pa[i][j]);
            float bj = bias[jt0 + tn * 4 + j];
            int mA = m0 + tm * 8 + 2 * i;
            int tA = mA >> 6, bA = mA & 63;
            g_Gx[(((size_t)tA * 3 + gate) * BB + bA) * HH + jt0 + tn * 4 + j] =
                __uint_as_float(lo) + bj;
            int mB = mA + 1;
            int tB = mB >> 6, bB = mB & 63;
            g_Gx[(((size_t)tB * 3 + gate) * BB + bB) * HH + jt0 + tn * 4 + j] =
                __uint_as_float(hi) + bj;
        }
    }
}

// =====================================================================================
// Phase 2: R15 skeleton, with (1) conflict-free fill STS mapping, (2) red-based step
// barriers with static targets (replay-safe via pre-init reset).
// Stage1: gate=w>>2, jt=w&3, full K, 32-val butterfly (R5 verbatim).
// Stage2: warp owns 4 cols, full K, pre-stage(m=16)+4 splits (R15-proven).
// =====================================================================================
__global__ void __launch_bounds__(NT, 1) phase2_gru(
    const float* __restrict__ h0in,
    const float* __restrict__ Wz,
    const float* __restrict__ Wr,
    const float* __restrict__ Wh,
    float* __restrict__ out)
{
    extern __shared__ float sm[];
    float* wzs  = sm;                     // [512][32] swizzled
    float* wrs  = wzs + HH * JC;
    float* whs  = wrs + HH * JC;
    float* hbuf = whs + HH * JC;          // [512][HPAD]
    float* z_s  = hbuf + HH * HPAD;       // [8][32]
    float* ho_s = z_s + GB * JC;          // [8][32]

    const int grp  = blockIdx.x >> 4;
    const int rank = blockIdx.x & 15;
    const int b0 = grp * GB;
    const int j0 = rank * JC;
    const int tid  = threadIdx.x;
    const int warp = tid >> 5;
    const int lane = tid & 31;

    // reset step counter (published by the init barrier's release below)
    if (tid == 0 && rank == 0)
        asm volatile("st.relaxed.gpu.global.u32 [%0], %1;"
                     :: "l"(&g_scnt[grp]), "r"(0u));

    // resident recurrent weights (rows DD..DD+511), float4-slot XOR swizzle
    for (int idx = tid; idx < HH * JC; idx += NT) {
        int k = idx >> 5, jl = idx & 31;
        int phys = k * JC + ((((jl >> 2) ^ (k & 7))) << 2) + (jl & 3);
        size_t goff = (size_t)(DD + k) * HH + j0 + jl;
        wzs[phys] = Wz[goff];
        wrs[phys] = Wr[goff];
        whs[phys] = Wh[goff];
    }
    init_barrier(grp);   // publishes counter reset + weights loaded

    const int gate1 = warp >> 2;            // stage1: 0=z, 1=r
    const int jt    = warp & 3;             // stage1 8-col tile
    const int slotA = (jt * 2) ^ (lane & 7);
    const int slotB = (jt * 2 + 1) ^ (lane & 7);
    const int slot2 = warp ^ (lane & 7);    // stage2: warp's 4-col float4 slot
    const int bp    = lane >> 3;            // stage1 owned b-pair
    const int jl_o  = jt * 8 + (lane & 7);  // stage1 owned column
    const int p2    = (lane & 15) >> 2;     // stage2 owned b-pair (lanes<16)
    const int c2    = warp * 4 + (lane & 3);// stage2 owned column
    const int fq    = lane >> 3;            // fill: k sub-offset 0..3
    const int fbo   = lane & 7;             // fill: batch element 0..7
    const int fk0   = warp * 64;            // fill: warp's 64-k slice

    for (int t = 0; t < TT; t++) {
        // ---- Gx prefetch (DRAM latency hidden under fill+dot1) ----
        float gx1lo, gx1hi, gx2lo = 0.f, gx2hi = 0.f;
        {
            size_t r1 = (((size_t)t * 3 + gate1) * BB + b0 + 2 * bp) * HH + j0 + jl_o;
            gx1lo = __ldg(&g_Gx[r1]);
            gx1hi = __ldg(&g_Gx[r1 + HH]);
            if (lane < 16) {
                size_t r2 = (((size_t)t * 3 + 2) * BB + b0 + 2 * p2) * HH + j0 + c2;
                gx2lo = __ldg(&g_Gx[r2]);
                gx2hi = __ldg(&g_Gx[r2 + HH]);
            }
        }

        // ---- fill hbuf with h: conflict-free STS (banks all distinct per instr) ----
        const float* hsrc = (t == 0) ? h0in : (const float*)g_h;
#pragma unroll
        for (int c = 0; c < 16; c++) {
            int k = fk0 + c * 4 + fq;
            hbuf[k * HPAD + fbo] = __ldcg(&hsrc[(size_t)(b0 + fbo) * HH + k]);
        }
        __syncthreads();

        // stash h_old for own columns
        { int b = tid >> 5, jl = tid & 31; ho_s[tid] = hbuf[(j0 + jl) * HPAD + b]; }

        // ================= stage 1 dot (full K=512 per warp) — R5 verbatim =========
        unsigned long long a2[32];
#pragma unroll
        for (int v = 0; v < 32; v++) a2[v] = 0ull;
        {
            const float4* wp = (const float4*)((gate1 ? wrs : wzs) + lane * JC);
            const char*   hp = (const char*)(hbuf + lane * HPAD);
#pragma unroll
            for (int i = 0; i < 16; i++) {
                float4 w0 = wp[slotA], w1 = wp[slotB];
                ulonglong2 hL = *(const ulonglong2*)hp;
                ulonglong2 hH = *(const ulonglong2*)(hp + 16);
                unsigned long long hb[4] = {hL.x, hL.y, hH.x, hH.y};
                unsigned long long wd[8];
                DUP_X2(wd[0], w0.x); DUP_X2(wd[1], w0.y);
                DUP_X2(wd[2], w0.z); DUP_X2(wd[3], w0.w);
                DUP_X2(wd[4], w1.x); DUP_X2(wd[5], w1.y);
                DUP_X2(wd[6], w1.z); DUP_X2(wd[7], w1.w);
#pragma unroll
                for (int p = 0; p < 4; p++)
#pragma unroll
                    for (int j = 0; j < 8; j++)
                        FMA_X2(a2[p * 8 + j], hb[p], wd[j], a2[p * 8 + j]);
                wp += 32 * JC / 4;
                hp += 32 * HPAD * 4;
            }
        }
#pragma unroll
        for (int s = 0; s < 5; s++) {
            const int m = 16 >> s, half = 16 >> s;
            bool up = (lane & m) != 0;
#pragma unroll
            for (int i = 0; i < half; i++) {
                unsigned long long send = up ? a2[i] : a2[i + half];
                unsigned long long r = __shfl_xor_sync(0xffffffffu, send, m);
                unsigned long long keep = up ? a2[i + half] : a2[i];
                ADD_X2(a2[i], keep, r);
            }
        }
        {
            unsigned lo, hi;
            UNPACK_X2(lo, hi, a2[0]);
            float s0 = fast_sigmoid(__uint_as_float(lo) + gx1lo);
            float s1 = fast_sigmoid(__uint_as_float(hi) + gx1hi);
            int bA = 2 * bp, bB = 2 * bp + 1;
            if (gate1 == 0) {
                z_s[bA * JC + jl_o] = s0;
                z_s[bB * JC + jl_o] = s1;
            } else {
                float rh0 = s0 * hbuf[(j0 + jl_o) * HPAD + bA];
                float rh1 = s1 * hbuf[(j0 + jl_o) * HPAD + bB];
                __stcg(&g_rh[(size_t)(b0 + bA) * HH + j0 + jl_o], rh0);
                __stcg(&g_rh[(size_t)(b0 + bB) * HH + j0 + jl_o], rh1);
            }
        }

        step_barrier(grp, (unsigned)(2 * t + 1) * GC);   // rh complete group-wide

        // ================= stage 2: fill hbuf with r*h (conflict-free) =============
#pragma unroll
        for (int c = 0; c < 16; c++) {
            int k = fk0 + c * 4 + fq;
            hbuf[k * HPAD + fbo] = __ldcg(&g_rh[(size_t)(b0 + fbo) * HH + k]);
        }
        __syncthreads();

        // stage-2 dot: warp owns 4 cols, FULL K=512 (R15-proven)
        unsigned long long b2[16];
#pragma unroll
        for (int v = 0; v < 16; v++) b2[v] = 0ull;
        {
            const float4* wp = (const float4*)(whs + lane * JC);
            const char*   hp = (const char*)(hbuf + lane * HPAD);
#pragma unroll
            for (int i = 0; i < 16; i++) {
                float4 w4 = wp[slot2];
                ulonglong2 hL = *(const ulonglong2*)hp;
                ulonglong2 hH = *(const ulonglong2*)(hp + 16);
                unsigned long long hb[4] = {hL.x, hL.y, hH.x, hH.y};
                unsigned long long wd[4];
                DUP_X2(wd[0], w4.x); DUP_X2(wd[1], w4.y);
                DUP_X2(wd[2], w4.z); DUP_X2(wd[3], w4.w);
#pragma unroll
                for (int p = 0; p < 4; p++)
#pragma unroll
                    for (int c = 0; c < 4; c++)
                        FMA_X2(b2[p * 4 + c], hb[p], wd[c], b2[p * 4 + c]);
                wp += 32 * JC / 4;
                hp += 32 * HPAD * 4;
            }
        }
#pragma unroll
        for (int i = 0; i < 16; i++) {
            unsigned long long r = __shfl_xor_sync(0xffffffffu, b2[i], 16);
            ADD_X2(b2[i], b2[i], r);
        }
#pragma unroll
        for (int s = 0; s < 4; s++) {
            const int m = 8 >> s, half = 8 >> s;
            bool up = (lane & m) != 0;
#pragma unroll
            for (int i = 0; i < half; i++) {
                unsigned long long send = up ? b2[i] : b2[i + half];
                unsigned long long r = __shfl_xor_sync(0xffffffffu, send, m);
                unsigned long long keep = up ? b2[i + half] : b2[i];
                ADD_X2(b2[i], keep, r);
            }
        }
        if (lane < 16) {
            unsigned lo, hi;
            UNPACK_X2(lo, hi, b2[0]);
            int bA = 2 * p2, bB = bA + 1;
            float ht0 = fast_tanh(__uint_as_float(lo) + gx2lo);
            float ht1 = fast_tanh(__uint_as_float(hi) + gx2hi);
            float z0 = z_s[bA * JC + c2], z1 = z_s[bB * JC + c2];
            float o0 = ho_s[bA * JC + c2], o1 = ho_s[bB * JC + c2];
            float hn0 = o0 + z0 * (ht0 - o0);
            float hn1 = o1 + z1 * (ht1 - o1);
            __stcg(&g_h[(size_t)(b0 + bA) * HH + j0 + c2], hn0);
            __stcg(&g_h[(size_t)(b0 + bB) * HH + j0 + c2], hn1);
            out[((size_t)t * BB + b0 + bA) * HH + j0 + c2] = hn0;
            out[((size_t)t * BB + b0 + bB) * HH + j0 + c2] = hn1;
        }

        step_barrier(grp, (unsigned)(2 * t + 2) * GC);   // h complete before next step
    }
}

// =====================================================================================
extern "C" void kernel_launch(void* const* d_in, const int* in_sizes, int n_in,
                              void* d_out, int out_size)
{
    const float* x  = (const float*)d_in[0];
    const float* h0 = (const float*)d_in[1];
    const float* Wz = (const float*)d_in[2];
    const float* bz = (const float*)d_in[3];
    const float* Wr = (const float*)d_in[4];
    const float* br = (const float*)d_in[5];
    const float* Wh = (const float*)d_in[6];
    const float* bh = (const float*)d_in[7];
    float* out = (float*)d_out;

    const int smem_bytes = (3 * HH * JC + HH * HPAD + 2 * GB * JC) * (int)sizeof(float);
    cudaFuncSetAttribute(phase2_gru, cudaFuncAttributeMaxDynamicSharedMemorySize, smem_bytes);

    dim3 g1((TT * BB) / 128, 24);
    phase1_gemm<<<g1, 256>>>(x, Wz, bz, Wr, br, Wh, bh);

    phase2_gru<<<NGROUPS * GC, NT, smem_bytes>>>(h0, Wz, Wr, Wh, out);
}